// round 1
// baseline (speedup 1.0000x reference)
#include <cuda_runtime.h>
#include <math.h>

// ---------------------------------------------------------------------------
// Problem constants
// ---------------------------------------------------------------------------
#define NNETS   5
#define DT_F    0.02f
#define NSTEPS  50

// LUT config: F_k tabulated on [TAB_LO, TAB_LO + NTAB*h], h = 1/16
#define NTAB     4096
#define TAB_LO   (-48.0f)
#define TAB_INVH 16.0f
#define XMIN     (-47.5f)   // fall back to exact loop outside [XMIN, XMAX]
#define XMAX     (206.5f)

// ---------------------------------------------------------------------------
// Device-global scratch (no allocations allowed)
// ---------------------------------------------------------------------------
__device__ float g_tab[NNETS * NTAB];
__device__ float g_W1[15];
__device__ float g_W2[45];
__device__ float g_W3[15];
__device__ float g_expb[NNETS];

// ---------------------------------------------------------------------------
// Exact 50-step Euler integration of one scalar node through net k
// ---------------------------------------------------------------------------
__device__ __forceinline__ float run_ode(float x,
                                         const float w1[3],
                                         const float w2[9],
                                         const float w3[3],
                                         float eb) {
    float node = x;
#pragma unroll 1
    for (int s = 0; s < NSTEPS; ++s) {
        float h0 = tanhf(node * w1[0]);
        float h1 = tanhf(node * w1[1]);
        float h2 = tanhf(node * w1[2]);
        float g0 = tanhf(fmaf(h2, w2[6], fmaf(h1, w2[3], h0 * w2[0])));
        float g1 = tanhf(fmaf(h2, w2[7], fmaf(h1, w2[4], h0 * w2[1])));
        float g2 = tanhf(fmaf(h2, w2[8], fmaf(h1, w2[5], h0 * w2[2])));
        float y  = fmaf(g2, w3[2], fmaf(g1, w3[1], g0 * w3[0])) + eb;
        node = fmaf(DT_F, y, node);
    }
    return node;
}

// ---------------------------------------------------------------------------
// Kernel 1: build per-net LUTs of the 50-step map F_k, stage weights
// ---------------------------------------------------------------------------
__global__ void build_tables_kernel(const float* __restrict__ W1,
                                    const float* __restrict__ W2,
                                    const float* __restrict__ W3,
                                    const float* __restrict__ b) {
    int idx = blockIdx.x * blockDim.x + threadIdx.x;

    // stage weights for the (rare) exact fallback path
    if (idx < 15) g_W1[idx] = W1[idx];
    if (idx < 45) g_W2[idx] = W2[idx];
    if (idx < 15) g_W3[idx] = W3[idx];
    if (idx < NNETS) g_expb[idx] = expf(b[idx]);

    if (idx >= NNETS * NTAB) return;
    int k = idx / NTAB;
    int j = idx - k * NTAB;

    float w1[3], w2[9], w3[3];
#pragma unroll
    for (int i = 0; i < 3; ++i) w1[i] = W1[k * 3 + i];
#pragma unroll
    for (int i = 0; i < 9; ++i) w2[i] = W2[k * 9 + i];
#pragma unroll
    for (int i = 0; i < 3; ++i) w3[i] = W3[k * 3 + i];
    float eb = expf(b[k]);

    float x = TAB_LO + (float)j * (1.0f / TAB_INVH);
    g_tab[idx] = run_ode(x, w1, w2, w3, eb);
}

// ---------------------------------------------------------------------------
// Rare exact fallback (out-of-table-range node values)
// ---------------------------------------------------------------------------
__device__ __noinline__ float slow_F(int k, float x) {
    float w1[3], w2[9], w3[3];
#pragma unroll
    for (int i = 0; i < 3; ++i) w1[i] = g_W1[k * 3 + i];
#pragma unroll
    for (int i = 0; i < 9; ++i) w2[i] = g_W2[k * 9 + i];
#pragma unroll
    for (int i = 0; i < 3; ++i) w3[i] = g_W3[k * 3 + i];
    return run_ode(x, w1, w2, w3, g_expb[k]);
}

__device__ __forceinline__ float eval_F(int k, float x) {
    if (x < XMIN || x > XMAX) return slow_F(k, x);
    float t = (x - TAB_LO) * TAB_INVH;
    int   i = (int)t;
    if (i > NTAB - 2) i = NTAB - 2;   // paranoia clamp
    float f = t - (float)i;
    const float* tb = g_tab + k * NTAB;
    float a0 = __ldg(tb + i);
    float a1 = __ldg(tb + i + 1);
    return fmaf(f, a1 - a0, a0);
}

// ---------------------------------------------------------------------------
// Kernel 2: eigenvalues + LUT + spectral-polynomial recombine
// ---------------------------------------------------------------------------
#define TPB 256

__global__ __launch_bounds__(TPB)
void ndpdt_main_kernel(const float* __restrict__ x,
                       float* __restrict__ out,
                       int P) {
    __shared__ float sx[TPB * 9];

    const int base = blockIdx.x * TPB;
    const int rem  = min(TPB, P - base);

    // cooperative coalesced float4 staging: rem*9 floats from x[base*9 ...]
    {
        const int nfloat = rem * 9;
        const int nf4    = nfloat >> 2;
        const float4* src = reinterpret_cast<const float4*>(x + (size_t)base * 9);
        float4* dst = reinterpret_cast<float4*>(sx);
        for (int i = threadIdx.x; i < nf4; i += TPB) dst[i] = src[i];
        // scalar tail (nfloat may not be a multiple of 4 in a final partial block)
        for (int i = (nf4 << 2) + threadIdx.x; i < nfloat; i += TPB)
            sx[i] = x[(size_t)base * 9 + i];
    }
    __syncthreads();

    const int p = base + threadIdx.x;
    if (p >= P) return;

    const float* m = sx + threadIdx.x * 9;   // stride-9: bank-conflict-free
    const float a00 = m[0], a01 = m[1], a02 = m[2];
    const float a11 = m[4], a12 = m[5], a22 = m[8];

    // ---- analytic symmetric 3x3 eigenvalues (trig / Smith) ----
    const float q  = (a00 + a11 + a22) * (1.0f / 3.0f);
    const float p1 = a01 * a01 + a02 * a02 + a12 * a12;
    const float d0 = a00 - q, d1d = a11 - q, d2d = a22 - q;
    const float p2 = d0 * d0 + d1d * d1d + d2d * d2d + 2.0f * p1;
    const float pp = sqrtf(p2 * (1.0f / 6.0f));
    const float invp = (pp > 1e-30f) ? (1.0f / pp) : 0.0f;

    const float b00 = d0 * invp, b11 = d1d * invp, b22 = d2d * invp;
    const float b01 = a01 * invp, b02 = a02 * invp, b12 = a12 * invp;
    float detB = b00 * (b11 * b22 - b12 * b12)
               - b01 * (b01 * b22 - b12 * b02)
               + b02 * (b01 * b12 - b11 * b02);
    float r = 0.5f * detB;
    r = fminf(fmaxf(r, -1.0f), 1.0f);

    const float phi = acosf(r) * (1.0f / 3.0f);
    float cph, sph;
    __sincosf(phi, &sph, &cph);          // fast path; refine below if needed
    // one precise recompute to keep eigenvalue error ~eps*||A||
    cph = cosf(phi);
    sph = sinf(phi);

    const float tau1 = q + 2.0f * pp * cph;                          // largest
    const float tau3 = q + pp * (-cph - 1.7320508075688772f * sph);  // smallest
    const float tau2 = 3.0f * q - tau1 - tau3;                       // middle

    // ---- invariants ----
    const float T  = 3.0f * q;           // trace
    const float n1 = tau1;
    const float n2 = tau1 + tau2;
    const float n3 = T;
    const float n4 = T * T;
    const float n5 = 1.5f * p2;          // = sum tau^2 - sum pairwise products

    // ---- 50-step MLP maps via LUT ----
    const float N1 = eval_F(0, n1);
    const float N2 = eval_F(1, n2);
    const float N3 = eval_F(2, n3);
    const float N4 = eval_F(3, n4);
    const float N5 = eval_F(4, n5);

    // ---- d coefficients ----
    const float cm = fmaf(2.0f * N4, T, N3);
    const float dd3 = fmaf(N5, 3.0f * tau3 - T, cm);
    const float dd2 = fmaf(N5, 3.0f * tau2 - T, cm + N2);
    const float dd1 = fmaf(N5, 3.0f * tau1 - T, cm + N2 + N1);

    // ---- quadratic spectral interpolant: dphi = alpha*I + beta*A + gamma*A^2 ----
    float e21 = fminf(tau2 - tau1, -1e-12f);
    float e32 = fminf(tau3 - tau2, -1e-12f);
    float e31 = fminf(tau3 - tau1, -1e-12f);
    const float c1  = (dd2 - dd1) / e21;
    const float c12 = (dd3 - dd2) / e32;
    const float c2  = (c12 - c1) / e31;

    const float alpha = fmaf(c2, tau1 * tau2, fmaf(-c1, tau1, dd1));
    const float beta  = fmaf(-c2, tau1 + tau2, c1);
    const float gamma = c2;

    // A^2 (symmetric, upper triangle)
    const float s00 = a00 * a00 + a01 * a01 + a02 * a02;
    const float s01 = a00 * a01 + a01 * a11 + a02 * a12;
    const float s02 = a00 * a02 + a01 * a12 + a02 * a22;
    const float s11 = a01 * a01 + a11 * a11 + a12 * a12;
    const float s12 = a01 * a02 + a11 * a12 + a12 * a22;
    const float s22 = a02 * a02 + a12 * a12 + a22 * a22;

    const size_t Ps = (size_t)P;
    out[p]          = fmaf(gamma, s00, fmaf(beta, a00, alpha));
    out[Ps + p]     = fmaf(gamma, s01, beta * a01);
    out[2 * Ps + p] = fmaf(gamma, s02, beta * a02);
    out[3 * Ps + p] = fmaf(gamma, s11, fmaf(beta, a11, alpha));
    out[4 * Ps + p] = fmaf(gamma, s12, beta * a12);
    out[5 * Ps + p] = fmaf(gamma, s22, fmaf(beta, a22, alpha));
}

// ---------------------------------------------------------------------------
// Launch
// ---------------------------------------------------------------------------
extern "C" void kernel_launch(void* const* d_in, const int* in_sizes, int n_in,
                              void* d_out, int out_size) {
    const float* x  = (const float*)d_in[0];   // (P, 3, 3)
    const float* W1 = (const float*)d_in[1];   // (5, 1, 3)
    const float* W2 = (const float*)d_in[2];   // (5, 3, 3)
    const float* W3 = (const float*)d_in[3];   // (5, 3, 1)
    const float* b  = (const float*)d_in[4];   // (5, 1, 1)
    float* out = (float*)d_out;                // 6 * P floats

    const int P = in_sizes[0] / 9;

    build_tables_kernel<<<(NNETS * NTAB + 255) / 256, 256>>>(W1, W2, W3, b);
    ndpdt_main_kernel<<<(P + TPB - 1) / TPB, TPB>>>(x, out, P);
}

// round 2
// speedup vs baseline: 1.2249x; 1.2249x over previous
#include <cuda_runtime.h>
#include <math.h>

// ---------------------------------------------------------------------------
// Problem constants
// ---------------------------------------------------------------------------
#define NNETS   5
#define DT_F    0.02f
#define NSTEPS  50

// LUT config: F_k tabulated on [TAB_LO, TAB_LO + NTAB*h], h = 1/16
#define NTAB     4096
#define TAB_LO   (-48.0f)
#define TAB_INVH 16.0f
#define XMIN     (-47.5f)   // fall back to exact loop outside [XMIN, XMAX]
#define XMAX     (206.5f)

// ---------------------------------------------------------------------------
// Device-global scratch (no allocations allowed)
// ---------------------------------------------------------------------------
__device__ float g_tab[NNETS * NTAB];
__device__ float g_W1[15];
__device__ float g_W2[45];
__device__ float g_W3[15];
__device__ float g_expb[NNETS];

// hardware tanh (MUFU.TANH, sm_75+): ~5e-4 rel err, attenuated by DT*W3 in the
// ODE step -> <=1e-4 absolute in the 50-step map, far under the 1e-3 budget.
__device__ __forceinline__ float htanh(float v) {
    float r;
    asm("tanh.approx.f32 %0, %1;" : "=f"(r) : "f"(v));
    return r;
}

// ---------------------------------------------------------------------------
// Exact 50-step Euler integration of one scalar node through net k
// ---------------------------------------------------------------------------
__device__ __forceinline__ float run_ode(float x,
                                         const float w1[3],
                                         const float w2[9],
                                         const float w3[3],
                                         float eb) {
    float node = x;
#pragma unroll 1
    for (int s = 0; s < NSTEPS; ++s) {
        float h0 = htanh(node * w1[0]);
        float h1 = htanh(node * w1[1]);
        float h2 = htanh(node * w1[2]);
        float g0 = htanh(fmaf(h2, w2[6], fmaf(h1, w2[3], h0 * w2[0])));
        float g1 = htanh(fmaf(h2, w2[7], fmaf(h1, w2[4], h0 * w2[1])));
        float g2 = htanh(fmaf(h2, w2[8], fmaf(h1, w2[5], h0 * w2[2])));
        float y  = fmaf(g2, w3[2], fmaf(g1, w3[1], g0 * w3[0])) + eb;
        node = fmaf(DT_F, y, node);
    }
    return node;
}

// ---------------------------------------------------------------------------
// Kernel 1: build per-net LUTs of the 50-step map F_k, stage weights
// ---------------------------------------------------------------------------
__global__ void build_tables_kernel(const float* __restrict__ W1,
                                    const float* __restrict__ W2,
                                    const float* __restrict__ W3,
                                    const float* __restrict__ b) {
    int idx = blockIdx.x * blockDim.x + threadIdx.x;

    // stage weights for the (rare) exact fallback path
    if (idx < 15) g_W1[idx] = W1[idx];
    if (idx < 45) g_W2[idx] = W2[idx];
    if (idx < 15) g_W3[idx] = W3[idx];
    if (idx < NNETS) g_expb[idx] = expf(b[idx]);

    if (idx >= NNETS * NTAB) return;
    int k = idx / NTAB;
    int j = idx - k * NTAB;

    float w1[3], w2[9], w3[3];
#pragma unroll
    for (int i = 0; i < 3; ++i) w1[i] = W1[k * 3 + i];
#pragma unroll
    for (int i = 0; i < 9; ++i) w2[i] = W2[k * 9 + i];
#pragma unroll
    for (int i = 0; i < 3; ++i) w3[i] = W3[k * 3 + i];
    float eb = expf(b[k]);

    float x = TAB_LO + (float)j * (1.0f / TAB_INVH);
    g_tab[idx] = run_ode(x, w1, w2, w3, eb);
}

// ---------------------------------------------------------------------------
// Rare exact fallback (out-of-table-range node values)
// ---------------------------------------------------------------------------
__device__ __noinline__ float slow_F(int k, float x) {
    float w1[3], w2[9], w3[3];
#pragma unroll
    for (int i = 0; i < 3; ++i) w1[i] = g_W1[k * 3 + i];
#pragma unroll
    for (int i = 0; i < 9; ++i) w2[i] = g_W2[k * 9 + i];
#pragma unroll
    for (int i = 0; i < 3; ++i) w3[i] = g_W3[k * 3 + i];
    return run_ode(x, w1, w2, w3, g_expb[k]);
}

__device__ __forceinline__ float eval_F(int k, float x) {
    if (x < XMIN || x > XMAX) return slow_F(k, x);
    float t = (x - TAB_LO) * TAB_INVH;
    int   i = (int)t;
    float f = t - (float)i;
    const float* tb = g_tab + k * NTAB;
    float a0 = __ldg(tb + i);
    float a1 = __ldg(tb + i + 1);
    return fmaf(f, a1 - a0, a0);
}

// ---------------------------------------------------------------------------
// Fast acos: Abramowitz-Stegun 4.4.46 style, |abs err| ~ 3e-8 on [0,1].
// acos(x) = sqrt(1-x)*P(x) for x>=0; acos(x) = pi - acos(-x) for x<0.
// ---------------------------------------------------------------------------
__device__ __forceinline__ float fast_acos(float x) {
    float a = fabsf(x);
    float p = -0.0012624911f;
    p = fmaf(p, a,  0.0066700901f);
    p = fmaf(p, a, -0.0170881256f);
    p = fmaf(p, a,  0.0308918810f);
    p = fmaf(p, a, -0.0501743046f);
    p = fmaf(p, a,  0.0889789874f);
    p = fmaf(p, a, -0.2145988016f);
    p = fmaf(p, a,  1.5707963050f);
    float t = sqrtf(fmaxf(1.0f - a, 0.0f)) * p;
    return (x >= 0.0f) ? t : (3.14159265358979f - t);
}

// ---------------------------------------------------------------------------
// Kernel 2: eigenvalues + LUT + spectral-polynomial recombine
// ---------------------------------------------------------------------------
#define TPB 256

__global__ __launch_bounds__(TPB, 6)
void ndpdt_main_kernel(const float* __restrict__ x,
                       float* __restrict__ out,
                       int P) {
    __shared__ float sx[TPB * 9];

    const int base = blockIdx.x * TPB;
    const int rem  = min(TPB, P - base);

    // cooperative coalesced float4 staging: rem*9 floats from x[base*9 ...]
    {
        const int nfloat = rem * 9;
        const int nf4    = nfloat >> 2;
        const float4* src = reinterpret_cast<const float4*>(x + (size_t)base * 9);
        float4* dst = reinterpret_cast<float4*>(sx);
        for (int i = threadIdx.x; i < nf4; i += TPB) dst[i] = src[i];
        for (int i = (nf4 << 2) + threadIdx.x; i < nfloat; i += TPB)
            sx[i] = x[(size_t)base * 9 + i];
    }
    __syncthreads();

    const int p = base + threadIdx.x;
    if (p >= P) return;

    const float* m = sx + threadIdx.x * 9;   // stride-9: bank-conflict-free
    const float a00 = m[0], a01 = m[1], a02 = m[2];
    const float a11 = m[4], a12 = m[5], a22 = m[8];

    // ---- analytic symmetric 3x3 eigenvalues (trig / Smith) ----
    const float q  = (a00 + a11 + a22) * (1.0f / 3.0f);
    const float p1 = a01 * a01 + a02 * a02 + a12 * a12;
    const float d0 = a00 - q, d1d = a11 - q, d2d = a22 - q;
    const float p2 = d0 * d0 + d1d * d1d + d2d * d2d + 2.0f * p1;
    const float pp = sqrtf(p2 * (1.0f / 6.0f));
    const float invp = (pp > 1e-30f) ? __fdividef(1.0f, pp) : 0.0f;

    const float b00 = d0 * invp, b11 = d1d * invp, b22 = d2d * invp;
    const float b01 = a01 * invp, b02 = a02 * invp, b12 = a12 * invp;
    float detB = b00 * (b11 * b22 - b12 * b12)
               - b01 * (b01 * b22 - b12 * b02)
               + b02 * (b01 * b12 - b11 * b02);
    float r = 0.5f * detB;
    r = fminf(fmaxf(r, -1.0f), 1.0f);

    const float phi = fast_acos(r) * (1.0f / 3.0f);
    float sph, cph;
    __sincosf(phi, &sph, &cph);   // phi in [0, pi/3]: MUFU fast path is accurate

    const float tau1 = q + 2.0f * pp * cph;                          // largest
    const float tau3 = q + pp * (-cph - 1.7320508075688772f * sph);  // smallest
    const float tau2 = 3.0f * q - tau1 - tau3;                       // middle

    // ---- invariants ----
    const float T  = 3.0f * q;           // trace
    const float n1 = tau1;
    const float n2 = tau1 + tau2;
    const float n3 = T;
    const float n4 = T * T;
    const float n5 = 1.5f * p2;          // = sum tau^2 - sum pairwise products

    // ---- 50-step MLP maps via LUT (10 independent gathers: good MLP) ----
    const float N1 = eval_F(0, n1);
    const float N2 = eval_F(1, n2);
    const float N3 = eval_F(2, n3);
    const float N4 = eval_F(3, n4);
    const float N5 = eval_F(4, n5);

    // ---- d coefficients ----
    const float cm = fmaf(2.0f * N4, T, N3);
    const float dd3 = fmaf(N5, 3.0f * tau3 - T, cm);
    const float dd2 = fmaf(N5, 3.0f * tau2 - T, cm + N2);
    const float dd1 = fmaf(N5, 3.0f * tau1 - T, cm + N2 + N1);

    // ---- quadratic spectral interpolant: dphi = alpha*I + beta*A + gamma*A^2 ----
    const float e21 = fminf(tau2 - tau1, -1e-12f);
    const float e32 = fminf(tau3 - tau2, -1e-12f);
    const float e31 = fminf(tau3 - tau1, -1e-12f);
    const float c1  = __fdividef(dd2 - dd1, e21);
    const float c12 = __fdividef(dd3 - dd2, e32);
    const float c2  = __fdividef(c12 - c1, e31);

    const float alpha = fmaf(c2, tau1 * tau2, fmaf(-c1, tau1, dd1));
    const float beta  = fmaf(-c2, tau1 + tau2, c1);
    const float gamma = c2;

    // A^2 (symmetric, upper triangle)
    const float s00 = a00 * a00 + a01 * a01 + a02 * a02;
    const float s01 = a00 * a01 + a01 * a11 + a02 * a12;
    const float s02 = a00 * a02 + a01 * a12 + a02 * a22;
    const float s11 = a01 * a01 + a11 * a11 + a12 * a12;
    const float s12 = a01 * a02 + a11 * a12 + a12 * a22;
    const float s22 = a02 * a02 + a12 * a12 + a22 * a22;

    const size_t Ps = (size_t)P;
    out[p]          = fmaf(gamma, s00, fmaf(beta, a00, alpha));
    out[Ps + p]     = fmaf(gamma, s01, beta * a01);
    out[2 * Ps + p] = fmaf(gamma, s02, beta * a02);
    out[3 * Ps + p] = fmaf(gamma, s11, fmaf(beta, a11, alpha));
    out[4 * Ps + p] = fmaf(gamma, s12, beta * a12);
    out[5 * Ps + p] = fmaf(gamma, s22, fmaf(beta, a22, alpha));
}

// ---------------------------------------------------------------------------
// Launch
// ---------------------------------------------------------------------------
extern "C" void kernel_launch(void* const* d_in, const int* in_sizes, int n_in,
                              void* d_out, int out_size) {
    const float* x  = (const float*)d_in[0];   // (P, 3, 3)
    const float* W1 = (const float*)d_in[1];   // (5, 1, 3)
    const float* W2 = (const float*)d_in[2];   // (5, 3, 3)
    const float* W3 = (const float*)d_in[3];   // (5, 3, 1)
    const float* b  = (const float*)d_in[4];   // (5, 1, 1)
    float* out = (float*)d_out;                // 6 * P floats

    const int P = in_sizes[0] / 9;

    build_tables_kernel<<<(NNETS * NTAB + 255) / 256, 256>>>(W1, W2, W3, b);
    ndpdt_main_kernel<<<(P + TPB - 1) / TPB, TPB>>>(x, out, P);
}

// round 4
// speedup vs baseline: 1.4936x; 1.2194x over previous
#include <cuda_runtime.h>
#include <math.h>

// ---------------------------------------------------------------------------
// Problem constants
// ---------------------------------------------------------------------------
#define NNETS   5
#define DT_F    0.02f
#define NSTEPS  50

// Per-net LUT: 256 entries over [LO_k, HI_k]
#define NTAB 256
#define LO0 (-16.0f)
#define HI0 ( 16.0f)
#define LO1 (-24.0f)
#define HI1 ( 24.0f)
#define LO2 (-24.0f)
#define HI2 ( 24.0f)
#define LO3 ( -4.0f)
#define HI3 (252.0f)
#define LO4 ( -4.0f)
#define HI4 (124.0f)
#define IVH(lo,hi) (255.0f / ((hi) - (lo)))

// ---------------------------------------------------------------------------
// Device-global scratch (no allocations allowed)
// ---------------------------------------------------------------------------
__device__ float g_tab[NNETS * NTAB];
__device__ float g_W1[15];
__device__ float g_W2[45];
__device__ float g_W3[15];
__device__ float g_expb[NNETS];

// hardware tanh (MUFU.TANH): ~5e-4 rel err, attenuated by DT*W3 per step.
__device__ __forceinline__ float htanh(float v) {
    float r;
    asm("tanh.approx.f32 %0, %1;" : "=f"(r) : "f"(v));
    return r;
}

// ---------------------------------------------------------------------------
// Exact 50-step Euler integration of one scalar node through net k
// ---------------------------------------------------------------------------
__device__ __forceinline__ float run_ode(float x,
                                         const float w1[3],
                                         const float w2[9],
                                         const float w3[3],
                                         float eb) {
    float node = x;
#pragma unroll 1
    for (int s = 0; s < NSTEPS; ++s) {
        float h0 = htanh(node * w1[0]);
        float h1 = htanh(node * w1[1]);
        float h2 = htanh(node * w1[2]);
        float g0 = htanh(fmaf(h2, w2[6], fmaf(h1, w2[3], h0 * w2[0])));
        float g1 = htanh(fmaf(h2, w2[7], fmaf(h1, w2[4], h0 * w2[1])));
        float g2 = htanh(fmaf(h2, w2[8], fmaf(h1, w2[5], h0 * w2[2])));
        float y  = fmaf(g2, w3[2], fmaf(g1, w3[1], g0 * w3[0])) + eb;
        node = fmaf(DT_F, y, node);
    }
    return node;
}

// ---------------------------------------------------------------------------
// Kernel 1: build per-net LUTs of the 50-step map F_k, stage weights
// ---------------------------------------------------------------------------
__global__ void build_tables_kernel(const float* __restrict__ W1,
                                    const float* __restrict__ W2,
                                    const float* __restrict__ W3,
                                    const float* __restrict__ b) {
    int idx = blockIdx.x * blockDim.x + threadIdx.x;

    if (idx < 15) g_W1[idx] = W1[idx];
    if (idx < 45) g_W2[idx] = W2[idx];
    if (idx < 15) g_W3[idx] = W3[idx];
    if (idx < NNETS) g_expb[idx] = expf(b[idx]);

    if (idx >= NNETS * NTAB) return;
    int k = idx >> 8;
    int j = idx & 255;

    const float lo_t[5] = {LO0, LO1, LO2, LO3, LO4};
    const float hi_t[5] = {HI0, HI1, HI2, HI3, HI4};
    float lo = lo_t[k], hi = hi_t[k];

    float w1[3], w2[9], w3[3];
#pragma unroll
    for (int i = 0; i < 3; ++i) w1[i] = W1[k * 3 + i];
#pragma unroll
    for (int i = 0; i < 9; ++i) w2[i] = W2[k * 9 + i];
#pragma unroll
    for (int i = 0; i < 3; ++i) w3[i] = W3[k * 3 + i];
    float eb = expf(b[k]);

    float x = lo + (hi - lo) * (1.0f / 255.0f) * (float)j;
    g_tab[idx] = run_ode(x, w1, w2, w3, eb);
}

// ---------------------------------------------------------------------------
// Rare exact fallback (out-of-table-range node values)
// ---------------------------------------------------------------------------
__device__ __noinline__ float slow_F(int k, float x) {
    float w1[3], w2[9], w3[3];
#pragma unroll
    for (int i = 0; i < 3; ++i) w1[i] = g_W1[k * 3 + i];
#pragma unroll
    for (int i = 0; i < 9; ++i) w2[i] = g_W2[k * 9 + i];
#pragma unroll
    for (int i = 0; i < 3; ++i) w3[i] = g_W3[k * 3 + i];
    return run_ode(x, w1, w2, w3, g_expb[k]);
}

// LUT lookup from shared memory; lo/invh are compile-time literals at call sites
__device__ __forceinline__ float eval_F(int k, float x, float lo, float invh,
                                        const float* __restrict__ stab) {
    float t = (x - lo) * invh;
    if (!(t >= 0.0f && t <= 255.0f)) return slow_F(k, x);   // essentially never
    int i = (int)t;
    if (i > NTAB - 2) i = NTAB - 2;
    float f = t - (float)i;
    const float* tb = stab + (k << 8);
    float a0 = tb[i];
    float a1 = tb[i + 1];
    return fmaf(f, a1 - a0, a0);
}

// ---------------------------------------------------------------------------
// Fast acos (|abs err| ~3e-8 on [-1,1])
// ---------------------------------------------------------------------------
__device__ __forceinline__ float fast_acos(float x) {
    float a = fabsf(x);
    float p = -0.0012624911f;
    p = fmaf(p, a,  0.0066700901f);
    p = fmaf(p, a, -0.0170881256f);
    p = fmaf(p, a,  0.0308918810f);
    p = fmaf(p, a, -0.0501743046f);
    p = fmaf(p, a,  0.0889789874f);
    p = fmaf(p, a, -0.2145988016f);
    p = fmaf(p, a,  1.5707963050f);
    float t = sqrtf(fmaxf(1.0f - a, 0.0f)) * p;
    return (x >= 0.0f) ? t : (3.14159265358979f - t);
}

// ---------------------------------------------------------------------------
// Per-point computation: eigenvalues + LUT + spectral recombine
// ---------------------------------------------------------------------------
__device__ __forceinline__ void compute_point(const float* __restrict__ m,
                                              const float* __restrict__ stab,
                                              float res[6]) {
    const float a00 = m[0], a01 = m[1], a02 = m[2];
    const float a11 = m[4], a12 = m[5], a22 = m[8];

    const float q  = (a00 + a11 + a22) * (1.0f / 3.0f);
    const float p1 = a01 * a01 + a02 * a02 + a12 * a12;
    const float d0 = a00 - q, d1d = a11 - q, d2d = a22 - q;
    const float p2 = d0 * d0 + d1d * d1d + d2d * d2d + 2.0f * p1;
    const float pp = sqrtf(p2 * (1.0f / 6.0f));
    const float invp = (pp > 1e-30f) ? __fdividef(1.0f, pp) : 0.0f;

    const float b00 = d0 * invp, b11 = d1d * invp, b22 = d2d * invp;
    const float b01 = a01 * invp, b02 = a02 * invp, b12 = a12 * invp;
    float detB = b00 * (b11 * b22 - b12 * b12)
               - b01 * (b01 * b22 - b12 * b02)
               + b02 * (b01 * b12 - b11 * b02);
    float r = 0.5f * detB;
    r = fminf(fmaxf(r, -1.0f), 1.0f);

    const float phi = fast_acos(r) * (1.0f / 3.0f);
    float sph, cph;
    __sincosf(phi, &sph, &cph);   // phi in [0, pi/3]

    const float tau1 = q + 2.0f * pp * cph;
    const float tau3 = q + pp * (-cph - 1.7320508075688772f * sph);
    const float tau2 = 3.0f * q - tau1 - tau3;

    const float T  = 3.0f * q;
    const float n5 = 1.5f * p2;

    const float N1 = eval_F(0, tau1,        LO0, IVH(LO0, HI0), stab);
    const float N2 = eval_F(1, tau1 + tau2, LO1, IVH(LO1, HI1), stab);
    const float N3 = eval_F(2, T,           LO2, IVH(LO2, HI2), stab);
    const float N4 = eval_F(3, T * T,       LO3, IVH(LO3, HI3), stab);
    const float N5 = eval_F(4, n5,          LO4, IVH(LO4, HI4), stab);

    const float cm  = fmaf(2.0f * N4, T, N3);
    const float dd3 = fmaf(N5, 3.0f * tau3 - T, cm);
    const float dd2 = fmaf(N5, 3.0f * tau2 - T, cm + N2);
    const float dd1 = fmaf(N5, 3.0f * tau1 - T, cm + N2 + N1);

    const float e21 = fminf(tau2 - tau1, -1e-12f);
    const float e32 = fminf(tau3 - tau2, -1e-12f);
    const float e31 = fminf(tau3 - tau1, -1e-12f);
    const float c1  = __fdividef(dd2 - dd1, e21);
    const float c12 = __fdividef(dd3 - dd2, e32);
    const float c2  = __fdividef(c12 - c1, e31);

    const float alpha = fmaf(c2, tau1 * tau2, fmaf(-c1, tau1, dd1));
    const float beta  = fmaf(-c2, tau1 + tau2, c1);
    const float gamma = c2;

    const float s00 = a00 * a00 + a01 * a01 + a02 * a02;
    const float s01 = a00 * a01 + a01 * a11 + a02 * a12;
    const float s02 = a00 * a02 + a01 * a12 + a02 * a22;
    const float s11 = a01 * a01 + a11 * a11 + a12 * a12;
    const float s12 = a01 * a02 + a11 * a12 + a12 * a22;
    const float s22 = a02 * a02 + a12 * a12 + a22 * a22;

    res[0] = fmaf(gamma, s00, fmaf(beta, a00, alpha));
    res[1] = fmaf(gamma, s01, beta * a01);
    res[2] = fmaf(gamma, s02, beta * a02);
    res[3] = fmaf(gamma, s11, fmaf(beta, a11, alpha));
    res[4] = fmaf(gamma, s12, beta * a12);
    res[5] = fmaf(gamma, s22, fmaf(beta, a22, alpha));
}

// ---------------------------------------------------------------------------
// Kernel 2: 2 points per thread, smem-staged inputs + smem LUT
// ---------------------------------------------------------------------------
#define TPB 256
#define PPB (2 * TPB)   // points per block

__global__ __launch_bounds__(TPB, 4)
void ndpdt_main_kernel(const float* __restrict__ x,
                       float* __restrict__ out,
                       int P) {
    __shared__ float sx[PPB * 9];           // 18 KB
    __shared__ float stab[NNETS * NTAB];    // 5 KB

    const int base = blockIdx.x * PPB;
    const int rem  = min(PPB, P - base);

    // stage LUT (1280 floats)
#pragma unroll
    for (int i = 0; i < NNETS * NTAB; i += TPB)
        stab[i + threadIdx.x] = g_tab[i + threadIdx.x];

    // stage inputs: rem*9 floats, coalesced float4
    {
        const int nfloat = rem * 9;
        const int nf4    = nfloat >> 2;
        const float4* src = reinterpret_cast<const float4*>(x + (size_t)base * 9);
        float4* dst = reinterpret_cast<float4*>(sx);
        for (int i = threadIdx.x; i < nf4; i += TPB) dst[i] = src[i];
        for (int i = (nf4 << 2) + threadIdx.x; i < nfloat; i += TPB)
            sx[i] = x[(size_t)base * 9 + i];
    }
    __syncthreads();

    const int t  = threadIdx.x;
    const int l0 = 2 * t;          // local point indices
    const int l1 = 2 * t + 1;
    const int p0 = base + l0;
    const size_t Ps = (size_t)P;

    if (l1 < rem) {
        // fast path: two points, float2 stores
        float ra[6], rb[6];
        compute_point(sx + l0 * 9, stab, ra);
        compute_point(sx + l1 * 9, stab, rb);
#pragma unroll
        for (int j = 0; j < 6; ++j) {
            float2 v = make_float2(ra[j], rb[j]);
            *reinterpret_cast<float2*>(out + (size_t)j * Ps + p0) = v;
        }
    } else if (l0 < rem) {
        float ra[6];
        compute_point(sx + l0 * 9, stab, ra);
#pragma unroll
        for (int j = 0; j < 6; ++j)
            out[(size_t)j * Ps + p0] = ra[j];
    }
}

// ---------------------------------------------------------------------------
// Launch
// ---------------------------------------------------------------------------
extern "C" void kernel_launch(void* const* d_in, const int* in_sizes, int n_in,
                              void* d_out, int out_size) {
    const float* x  = (const float*)d_in[0];   // (P, 3, 3)
    const float* W1 = (const float*)d_in[1];   // (5, 1, 3)
    const float* W2 = (const float*)d_in[2];   // (5, 3, 3)
    const float* W3 = (const float*)d_in[3];   // (5, 3, 1)
    const float* b  = (const float*)d_in[4];   // (5, 1, 1)
    float* out = (float*)d_out;                // 6 * P floats

    const int P = in_sizes[0] / 9;

    build_tables_kernel<<<(NNETS * NTAB + 255) / 256, 256>>>(W1, W2, W3, b);
    ndpdt_main_kernel<<<(P + PPB - 1) / PPB, TPB>>>(x, out, P);
}